// round 7
// baseline (speedup 1.0000x reference)
#include <cuda_runtime.h>
#include <cstdint>

// EmbeddingDropout: out[row, :] = mask(v,:) ? weight[v,:] * (1/0.9) : 0, v = words[row]
// Mask reproduces jax.random.bernoulli(jax.random.key(42), 0.9, (V, D)) under the
// partitionable threefry scheme: bits(i) = fold(threefry2x32((0,42), hi=0, lo=i)),
// keep iff bits < 0xE6666600. Verified bit-exact (R4 rel_err = 0.0).
// words ships as int32 (JAX x64 disabled downgrades int64 -> int32).
//
// Pipe-balancing: rotl(x,r) = lo|hi of mul.wide.u32(x, 1<<r). The multiplier is
// loaded from __constant__ so ptxas CANNOT strength-reduce the multiply back to
// SHF; mul.wide is inline PTX so the IMAD.WIDE.U32 (fma pipe) is guaranteed.
// This evicts 20 SHF/elem from the saturated alu pipe (R4: alu=87.6%, fma=23.8%).

__constant__ uint32_t ROT_MUL[8] = {
    1u << 13, 1u << 15, 1u << 26, 1u << 6,    // rotation group A
    1u << 17, 1u << 29, 1u << 16, 1u << 24    // rotation group B
};

__device__ __forceinline__ uint32_t rot_via_mul(uint32_t x, uint32_t m, uint32_t xr) {
    // returns rotl(x, log2(m)) ^ xr  — OR+XOR fuses to one LOP3
    uint64_t p;
    asm("mul.wide.u32 %0, %1, %2;" : "=l"(p) : "r"(x), "r"(m));
    return ((uint32_t)p | (uint32_t)(p >> 32)) ^ xr;
}

__device__ __forceinline__ uint32_t threefry_fold(uint32_t ctr, const uint32_t* m) {
    // key = (0, 42); ks = {0, 42, 0x1BD11BDA ^ 0 ^ 42 = 0x1BD11BF0}
    const uint32_t KS1 = 42u;
    const uint32_t KS2 = 0x1BD11BF0u;
    uint32_t x0 = 0u;          // counts_hi (0) + ks[0] (0)
    uint32_t x1 = ctr + KS1;   // counts_lo + ks[1]
#define TF_RND(mi) { x0 += x1; x1 = rot_via_mul(x1, m[mi], x0); }
    TF_RND(0) TF_RND(1) TF_RND(2) TF_RND(3)      // rot 13,15,26,6
    x0 += KS1;  x1 += KS2 + 1u;
    TF_RND(4) TF_RND(5) TF_RND(6) TF_RND(7)      // rot 17,29,16,24
    x0 += KS2;  x1 += 0u  + 2u;
    TF_RND(0) TF_RND(1) TF_RND(2) TF_RND(3)
    x0 += 0u;   x1 += KS1 + 3u;
    TF_RND(4) TF_RND(5) TF_RND(6) TF_RND(7)
    x0 += KS1;  x1 += KS2 + 4u;
    TF_RND(0) TF_RND(1) TF_RND(2) TF_RND(3)
    x0 += KS2;  x1 += 0u  + 5u;
#undef TF_RND
    return x0 ^ x1;   // 32-bit XOR fold (partitionable random_bits)
}

__global__ void __launch_bounds__(256)
embedding_dropout_kernel(const int* __restrict__ words,
                         const float4* __restrict__ weight,
                         float4* __restrict__ out)
{
    const uint32_t KEEP_THRESH = 0xE6666600u;   // (0x733333 << 9): u < 0.9f
    const float    INV_KEEP    = 1.0f / 0.9f;

    // Load opaque rotation multipliers once (LDC); reused by all 20x8 rounds.
    uint32_t m[8];
#pragma unroll
    for (int i = 0; i < 8; i++) m[i] = ROT_MUL[i];

    // 256 threads / block, 2 rows / block; each half-block (128 lanes) does one
    // row; each thread does 8 elements as two coalesced float4s 512 floats apart.
    int tid  = threadIdx.x;
    int row  = (blockIdx.x << 1) + (tid >> 7);
    int lane = tid & 127;                       // 0..127 within the row

    uint32_t v = (uint32_t)words[row];          // vocab id (broadcast within half-block)
    uint32_t base = v * 1024u + (uint32_t)(lane << 2);   // flat index into [V, D]

    const float4* wrow = weight + (size_t)v * 256u;
    float4 w0 = wrow[lane];                     // elems [lane*4 .. +3]
    float4 w1 = wrow[lane + 128];               // elems [lane*4+512 .. +3]

    // 8 independent threefry chains -> deep ILP on the serial round dependency
    uint32_t b[8];
#pragma unroll
    for (int k = 0; k < 4; k++) b[k]     = threefry_fold(base + (uint32_t)k, m);
#pragma unroll
    for (int k = 0; k < 4; k++) b[4 + k] = threefry_fold(base + 512u + (uint32_t)k, m);

    float4 r0, r1;
    r0.x = (b[0] < KEEP_THRESH) ? w0.x * INV_KEEP : 0.0f;
    r0.y = (b[1] < KEEP_THRESH) ? w0.y * INV_KEEP : 0.0f;
    r0.z = (b[2] < KEEP_THRESH) ? w0.z * INV_KEEP : 0.0f;
    r0.w = (b[3] < KEEP_THRESH) ? w0.w * INV_KEEP : 0.0f;
    r1.x = (b[4] < KEEP_THRESH) ? w1.x * INV_KEEP : 0.0f;
    r1.y = (b[5] < KEEP_THRESH) ? w1.y * INV_KEEP : 0.0f;
    r1.z = (b[6] < KEEP_THRESH) ? w1.z * INV_KEEP : 0.0f;
    r1.w = (b[7] < KEEP_THRESH) ? w1.w * INV_KEEP : 0.0f;

    float4* orow = out + (size_t)row * 256u;
    orow[lane]       = r0;
    orow[lane + 128] = r1;
}

extern "C" void kernel_launch(void* const* d_in, const int* in_sizes, int n_in,
                              void* d_out, int out_size) {
    const int*    words  = (const int*)d_in[0];     // [B*S] int32
    const float4* weight = (const float4*)d_in[1];  // [V, D] fp32
    float4*       out    = (float4*)d_out;          // [B*S, D] fp32

    int n_rows = in_sizes[0];                        // B*S = 16384 (even)
    embedding_dropout_kernel<<<n_rows / 2, 256>>>(words, weight, out);
}